// round 9
// baseline (speedup 1.0000x reference)
#include <cuda_runtime.h>
#include <cstdint>

// SemiConv2d: 5x5 max-plus dilation, 'same' padding with -inf.
// input:  (16, 64, 256, 256) fp32 -> 1024 independent 256x256 images
// kernel: (5, 5) fp32
//
// Row-streaming, 5 rotating accumulator slots, 4 cols/thread, software-
// prefetched double-buffered loads (R6), boundary peeling (R7), best grid
// 2048x128 / 64-row strips (R7; single-wave grids lost twice: R5, R8).
// R9 change: NARROW LOADS + OCCUPANCY. Only 8 of the 12 loaded floats per
// row are ever used (cols j0-2..j0+5). Load float2+float4+float2 instead of
// 3x float4: -8 buffer registers (48->40 regs -> 12 blocks/SM via
// __launch_bounds__(128,12)) and -33% L1 request bytes. More resident
// warps = the variable R8 proved matters.

#define IMG_H 256
#define IMG_W 256

__device__ __align__(16) float g_ninf[16];

__global__ void fill_ninf_kernel() {
    g_ninf[threadIdx.x] = __int_as_float(0xff800000u);
}

__global__ void __launch_bounds__(128, 12) dil5x5_kernel(
    const float* __restrict__ x,
    const float* __restrict__ kw,
    float* __restrict__ out)
{
    const int lane   = threadIdx.x & 31;
    const int wlocal = threadIdx.x >> 5;
    const int w      = blockIdx.x * 4 + wlocal;   // warp-task id, 0..8191

    const int img   = w >> 3;          // 0..1023
    const int strip = (w >> 1) & 3;    // 0..3  -> 64-row strip
    const int half  = w & 1;           // 0..1  -> 128-col half

    const int i0 = strip << 6;                    // first output row of strip
    const int j0 = (half << 7) + (lane << 2);     // first of 4 output cols

    float k[25];
#pragma unroll
    for (int t = 0; t < 25; ++t) k[t] = kw[t];

    const float NI = __int_as_float(0xff800000u);

    float acc[5][4];
#pragma unroll
    for (int q = 0; q < 5; ++q)
#pragma unroll
        for (int c = 0; c < 4; ++c) acc[q][c] = NI;

    const float* xim = x   + (size_t)img * (IMG_H * IMG_W);
    float*       oim = out + (size_t)img * (IMG_H * IMG_W);

    // Column-halo validity (loop-invariant). A = cols j0-2,j0-1: invalid
    // only when j0==0. B = cols j0..j0+3: always valid. C = cols j0+4,
    // j0+5: invalid only when j0==252.
    const bool c0ok = (j0 != 0);
    const bool c2ok = (j0 != 252);

    // Row-halo validity: rows i0-2,i0-1 exist unless strip==0; rows
    // i0+64,i0+65 exist unless strip==3.
    const bool topok = (strip != 0);
    const bool botok = (strip != 3);

    const float2 NIV2 = make_float2(NI, NI);
    const float4 NIV4 = make_float4(NI, NI, NI, NI);
    // Double-buffered row registers; edge-lane A/C stay -inf forever.
    float2 Ab[2] = {NIV2, NIV2};
    float4 Bb[2] = {NIV4, NIV4};
    float2 Cb[2] = {NIV2, NIV2};

    const float* ninf = g_ninf;   // 16 floats of -inf (16B aligned)

    // Load a row into buffer DSTP. RP points at col j0-4 (16B aligned);
    // offsets: A=+2 (8B ok), B=+4 (16B ok), C=+8 (16B ok). The -inf scratch
    // row satisfies the same alignments.
#define PREF(DSTP, RP)                                                       \
    {                                                                        \
        const float* _rp = (RP);                                             \
        if (c0ok) Ab[DSTP] = *(const float2*)(_rp + 2);                      \
        Bb[DSTP] = *(const float4*)(_rp + 4);                                \
        if (c2ok) Cb[DSTP] = *(const float2*)(_rp + 8);                      \
    }

    // Apply buffer CUR to the 5 rotating slots (phase PH); optionally store
    // the completed slot (slot PH finishes kernel row u=4 this step).
    // X[m] = col j0-2+m ; tap col j0+c+v-2 -> X[c+v].
#define MATH(PH, CUR, STOREF, OPTR)                                          \
    {                                                                        \
        float X[8] = {Ab[CUR].x, Ab[CUR].y,                                  \
                      Bb[CUR].x, Bb[CUR].y, Bb[CUR].z, Bb[CUR].w,            \
                      Cb[CUR].x, Cb[CUR].y};                                 \
        _Pragma("unroll")                                                    \
        for (int q = 0; q < 5; ++q) {                                        \
            const int d = (q - (PH) + 5) % 5;   /* compile-time */           \
            const int u = 4 - d;                /* kernel row   */           \
            if (d == 4) {                                                    \
                _Pragma("unroll")                                            \
                for (int c = 0; c < 4; ++c)                                  \
                    acc[q][c] = X[c] + k[u * 5 + 0];                         \
                _Pragma("unroll")                                            \
                for (int v = 1; v < 5; ++v)                                  \
                    _Pragma("unroll")                                        \
                    for (int c = 0; c < 4; ++c)                              \
                        acc[q][c] = fmaxf(acc[q][c], X[c + v] + k[u * 5 + v]); \
            } else {                                                         \
                _Pragma("unroll")                                            \
                for (int v = 0; v < 5; ++v)                                  \
                    _Pragma("unroll")                                        \
                    for (int c = 0; c < 4; ++c)                              \
                        acc[q][c] = fmaxf(acc[q][c], X[c + v] + k[u * 5 + v]); \
            }                                                                \
        }                                                                    \
        if (STOREF)                                                          \
            *(float4*)(OPTR) = make_float4(acc[PH][0], acc[PH][1],           \
                                           acc[PH][2], acc[PH][3]);          \
    }

    // pbase -> row i0-2, col j0-4
    const float* pbase = xim + (ptrdiff_t)(i0 - 2) * IMG_W + (j0 - 4);

    // Prologue: buffer 0 <- row i0-2 (or -inf for the top strip).
    PREF(0, topok ? pbase : ninf)

    // Head, steps s=0..3 (consume rows i0-2..i0+1, no stores).
    PREF(1, topok ? pbase + 1 * IMG_W : ninf)  MATH(0, 0, 0, oim)
    PREF(0, pbase + 2 * IMG_W)                 MATH(1, 1, 0, oim)
    PREF(1, pbase + 3 * IMG_W)                 MATH(2, 0, 0, oim)
    PREF(0, pbase + 4 * IMG_W)                 MATH(3, 1, 0, oim)

    // Steady state, steps s=4..63: all loads/stores unconditional,
    // immediate offsets, pointers bumped once per 10 steps.
    const float* pb = pbase + 5 * IMG_W;             // row i0+3 (first prefetch)
    float*       ob = oim + (size_t)i0 * IMG_W + j0; // row i0 (first store)
    for (int g = 0; g < 6; ++g) {
        PREF(1, pb + 0 * IMG_W)  MATH(4, 0, 1, ob + 0 * IMG_W)
        PREF(0, pb + 1 * IMG_W)  MATH(0, 1, 1, ob + 1 * IMG_W)
        PREF(1, pb + 2 * IMG_W)  MATH(1, 0, 1, ob + 2 * IMG_W)
        PREF(0, pb + 3 * IMG_W)  MATH(2, 1, 1, ob + 3 * IMG_W)
        PREF(1, pb + 4 * IMG_W)  MATH(3, 0, 1, ob + 4 * IMG_W)
        PREF(0, pb + 5 * IMG_W)  MATH(4, 1, 1, ob + 5 * IMG_W)
        PREF(1, pb + 6 * IMG_W)  MATH(0, 0, 1, ob + 6 * IMG_W)
        PREF(0, pb + 7 * IMG_W)  MATH(1, 1, 1, ob + 7 * IMG_W)
        PREF(1, pb + 8 * IMG_W)  MATH(2, 0, 1, ob + 8 * IMG_W)
        PREF(0, pb + 9 * IMG_W)  MATH(3, 1, 1, ob + 9 * IMG_W)
        pb += 10 * IMG_W;
        ob += 10 * IMG_W;
    }
    // After loop: pb -> row i0+63 (next prefetch), ob -> output row i0+60.

    // Tail, steps s=64..67 (phases 4,0,1,2; CUR 0,1,0,1): prefetch rows
    // i0+63 (valid), i0+64, i0+65 (valid unless bottom strip), none.
    PREF(1, pb + 0 * IMG_W)                    MATH(4, 0, 1, ob + 0 * IMG_W)
    PREF(0, botok ? pb + 1 * IMG_W : ninf)     MATH(0, 1, 1, ob + 1 * IMG_W)
    PREF(1, botok ? pb + 2 * IMG_W : ninf)     MATH(1, 0, 1, ob + 2 * IMG_W)
    /* no prefetch for the final step */       MATH(2, 1, 1, ob + 3 * IMG_W)

#undef PREF
#undef MATH
}

extern "C" void kernel_launch(void* const* d_in, const int* in_sizes, int n_in,
                              void* d_out, int out_size) {
    const float* x  = (const float*)d_in[0];  // (16,64,256,256)
    const float* kw = (const float*)d_in[1];  // (5,5)
    float* out = (float*)d_out;
    fill_ninf_kernel<<<1, 16>>>();
    // 8192 warp-tasks = 1024 images x 4 row-strips x 2 column-halves
    dil5x5_kernel<<<2048, 128>>>(x, kw, out);
}

// round 10
// speedup vs baseline: 1.3777x; 1.3777x over previous
#include <cuda_runtime.h>
#include <cstdint>

// SemiConv2d: 5x5 max-plus dilation, 'same' padding with -inf.
// input:  (16, 64, 256, 256) fp32 -> 1024 independent 256x256 images
// kernel: (5, 5) fp32
//
// Row-streaming, 5 rotating accumulator slots, 4 cols/thread (float4 I/O),
// software-prefetched double-buffered loads (R6), boundary peeling (R7).
// R10 change: FINER BLOCKS to shrink the end-of-kernel occupancy ramp.
// 32-row strips -> 16384 warp-tasks over 4096 blocks; with 10 resident
// blocks/SM the tail generation is 1/3 of the run at 77% fill instead of
// 1/2 at 38% (time-avg occ ~92% vs ~69%), at +5.9% warm-up work.
// R9's narrow loads are fully reverted (they doubled L1 wavefronts).

#define IMG_H 256
#define IMG_W 256

__device__ __align__(16) float g_ninf[16];

__global__ void fill_ninf_kernel() {
    g_ninf[threadIdx.x] = __int_as_float(0xff800000u);
}

__global__ void __launch_bounds__(128) dil5x5_kernel(
    const float* __restrict__ x,
    const float* __restrict__ kw,
    float* __restrict__ out)
{
    const int lane   = threadIdx.x & 31;
    const int wlocal = threadIdx.x >> 5;
    const int w      = blockIdx.x * 4 + wlocal;   // warp-task id, 0..16383

    const int img   = w >> 4;          // 0..1023
    const int strip = (w >> 1) & 7;    // 0..7  -> 32-row strip
    const int half  = w & 1;           // 0..1  -> 128-col half

    const int i0 = strip << 5;                    // first output row of strip
    const int j0 = (half << 7) + (lane << 2);     // first of 4 output cols

    float k[25];
#pragma unroll
    for (int t = 0; t < 25; ++t) k[t] = kw[t];

    const float NI = __int_as_float(0xff800000u);

    float acc[5][4];
#pragma unroll
    for (int q = 0; q < 5; ++q)
#pragma unroll
        for (int c = 0; c < 4; ++c) acc[q][c] = NI;

    const float* xim = x   + (size_t)img * (IMG_H * IMG_W);
    float*       oim = out + (size_t)img * (IMG_H * IMG_W);

    // Column-halo validity (loop-invariant). A covers cols j0-4..j0-1 (we
    // use j0-2,j0-1): invalid only when j0==0. C covers j0+4..j0+7 (we use
    // j0+4,j0+5): invalid only when j0==252. B always valid.
    const bool c0ok = (j0 != 0);
    const bool c2ok = (j0 != 252);

    // Row-halo validity: rows i0-2,i0-1 exist unless strip==0; rows
    // i0+32,i0+33 exist unless strip==7 (bottom strip).
    const bool topok = (strip != 0);
    const bool botok = (strip != 7);

    const float4 NIV = make_float4(NI, NI, NI, NI);
    float4 Ab[2] = {NIV, NIV}, Bb[2] = {NIV, NIV}, Cb[2] = {NIV, NIV};

    const float* ninf = g_ninf;   // 16 floats of -inf

    // Load a row (base pointer at col j0-4) into buffer DSTP.
#define PREF(DSTP, RP)                                                       \
    {                                                                        \
        const float* _rp = (RP);                                             \
        if (c0ok) Ab[DSTP] = *(const float4*)(_rp);                          \
        Bb[DSTP] = *(const float4*)(_rp + 4);                                \
        if (c2ok) Cb[DSTP] = *(const float4*)(_rp + 8);                      \
    }

    // Apply buffer CUR to the 5 rotating slots (phase PH); optionally store
    // the completed slot (slot PH finishes kernel row u=4 this step).
#define MATH(PH, CUR, STOREF, OPTR)                                          \
    {                                                                        \
        float X[12] = {Ab[CUR].x, Ab[CUR].y, Ab[CUR].z, Ab[CUR].w,           \
                       Bb[CUR].x, Bb[CUR].y, Bb[CUR].z, Bb[CUR].w,           \
                       Cb[CUR].x, Cb[CUR].y, Cb[CUR].z, Cb[CUR].w};          \
        _Pragma("unroll")                                                    \
        for (int q = 0; q < 5; ++q) {                                        \
            const int d = (q - (PH) + 5) % 5;   /* compile-time */           \
            const int u = 4 - d;                /* kernel row   */           \
            if (d == 4) {                                                    \
                _Pragma("unroll")                                            \
                for (int c = 0; c < 4; ++c)                                  \
                    acc[q][c] = X[c + 2] + k[u * 5 + 0];                     \
                _Pragma("unroll")                                            \
                for (int v = 1; v < 5; ++v)                                  \
                    _Pragma("unroll")                                        \
                    for (int c = 0; c < 4; ++c)                              \
                        acc[q][c] = fmaxf(acc[q][c], X[c + v + 2] + k[u * 5 + v]); \
            } else {                                                         \
                _Pragma("unroll")                                            \
                for (int v = 0; v < 5; ++v)                                  \
                    _Pragma("unroll")                                        \
                    for (int c = 0; c < 4; ++c)                              \
                        acc[q][c] = fmaxf(acc[q][c], X[c + v + 2] + k[u * 5 + v]); \
            }                                                                \
        }                                                                    \
        if (STOREF)                                                          \
            *(float4*)(OPTR) = make_float4(acc[PH][0], acc[PH][1],           \
                                           acc[PH][2], acc[PH][3]);          \
    }

    // pbase -> row i0-2, col j0-4
    const float* pbase = xim + (ptrdiff_t)(i0 - 2) * IMG_W + (j0 - 4);

    // Prologue: buffer 0 <- row i0-2 (or -inf for the top strip).
    PREF(0, topok ? pbase : ninf)

    // Head, steps s=0..3 (consume rows i0-2..i0+1, no stores).
    // Step s: phase s%5, CUR s&1, prefetch row i0+s-1 into CUR^1.
    PREF(1, topok ? pbase + 1 * IMG_W : ninf)  MATH(0, 0, 0, oim)
    PREF(0, pbase + 2 * IMG_W)                 MATH(1, 1, 0, oim)
    PREF(1, pbase + 3 * IMG_W)                 MATH(2, 0, 0, oim)
    PREF(0, pbase + 4 * IMG_W)                 MATH(3, 1, 0, oim)

    // Steady state, steps s=4..23 (2 x 10): unconditional loads/stores,
    // immediate offsets, pointers bumped once per 10 steps.
    const float* pb = pbase + 5 * IMG_W;             // row i0+3 (first prefetch)
    float*       ob = oim + (size_t)i0 * IMG_W + j0; // row i0 (first store)
    for (int g = 0; g < 2; ++g) {
        PREF(1, pb + 0 * IMG_W)  MATH(4, 0, 1, ob + 0 * IMG_W)
        PREF(0, pb + 1 * IMG_W)  MATH(0, 1, 1, ob + 1 * IMG_W)
        PREF(1, pb + 2 * IMG_W)  MATH(1, 0, 1, ob + 2 * IMG_W)
        PREF(0, pb + 3 * IMG_W)  MATH(2, 1, 1, ob + 3 * IMG_W)
        PREF(1, pb + 4 * IMG_W)  MATH(3, 0, 1, ob + 4 * IMG_W)
        PREF(0, pb + 5 * IMG_W)  MATH(4, 1, 1, ob + 5 * IMG_W)
        PREF(1, pb + 6 * IMG_W)  MATH(0, 0, 1, ob + 6 * IMG_W)
        PREF(0, pb + 7 * IMG_W)  MATH(1, 1, 1, ob + 7 * IMG_W)
        PREF(1, pb + 8 * IMG_W)  MATH(2, 0, 1, ob + 8 * IMG_W)
        PREF(0, pb + 9 * IMG_W)  MATH(3, 1, 1, ob + 9 * IMG_W)
        pb += 10 * IMG_W;
        ob += 10 * IMG_W;
    }
    // After loop: pb -> row i0+23 (next prefetch), ob -> output row i0+20.

    // Remainder, steps s=24..32 (9 steps, prefetch rows i0+23..i0+31, all
    // inside the image for every strip).
    PREF(1, pb + 0 * IMG_W)  MATH(4, 0, 1, ob + 0 * IMG_W)
    PREF(0, pb + 1 * IMG_W)  MATH(0, 1, 1, ob + 1 * IMG_W)
    PREF(1, pb + 2 * IMG_W)  MATH(1, 0, 1, ob + 2 * IMG_W)
    PREF(0, pb + 3 * IMG_W)  MATH(2, 1, 1, ob + 3 * IMG_W)
    PREF(1, pb + 4 * IMG_W)  MATH(3, 0, 1, ob + 4 * IMG_W)
    PREF(0, pb + 5 * IMG_W)  MATH(4, 1, 1, ob + 5 * IMG_W)
    PREF(1, pb + 6 * IMG_W)  MATH(0, 0, 1, ob + 6 * IMG_W)
    PREF(0, pb + 7 * IMG_W)  MATH(1, 1, 1, ob + 7 * IMG_W)
    PREF(1, pb + 8 * IMG_W)  MATH(2, 0, 1, ob + 8 * IMG_W)

    // Tail, steps s=33..35: prefetch rows i0+32, i0+33 (valid unless
    // bottom strip), then the final math-only step.
    PREF(0, botok ? pb + 9 * IMG_W : ninf)     MATH(3, 1, 1, ob + 9 * IMG_W)
    PREF(1, botok ? pb + 10 * IMG_W : ninf)    MATH(4, 0, 1, ob + 10 * IMG_W)
    /* no prefetch for the final step */       MATH(0, 1, 1, ob + 11 * IMG_W)

#undef PREF
#undef MATH
}

extern "C" void kernel_launch(void* const* d_in, const int* in_sizes, int n_in,
                              void* d_out, int out_size) {
    const float* x  = (const float*)d_in[0];  // (16,64,256,256)
    const float* kw = (const float*)d_in[1];  // (5,5)
    float* out = (float*)d_out;
    fill_ninf_kernel<<<1, 16>>>();
    // 16384 warp-tasks = 1024 images x 8 row-strips x 2 column-halves
    dil5x5_kernel<<<4096, 128>>>(x, kw, out);
}

// round 11
// speedup vs baseline: 1.3840x; 1.0046x over previous
#include <cuda_runtime.h>
#include <cstdint>

// SemiConv2d: 5x5 max-plus dilation, 'same' padding with -inf.
// input:  (16, 64, 256, 256) fp32 -> 1024 independent 256x256 images
// kernel: (5, 5) fp32
//
// Row-streaming, 5 rotating accumulator slots, 4 cols/thread (float4 I/O),
// software-prefetched double-buffered loads (R6), boundary peeling (R7),
// 64-row strips (best: R7). R10's finer strips reverted (work overhead,
// no smoothing gain).
// R11 changes:
//  1) MASKED head/tail: head steps skip slots not yet initialized, tail
//     steps skip slots that will never emit -> -5.8% of all math ops.
//  2) 64-thread blocks (2 warps = the two column-halves of one strip):
//     21 blocks/SM @48 regs = 42 warps/SM (vs 40) and 2x finer tail
//     quantization, with identical per-warp code.

#define IMG_H 256
#define IMG_W 256

__device__ __align__(16) float g_ninf[16];

__global__ void fill_ninf_kernel() {
    g_ninf[threadIdx.x] = __int_as_float(0xff800000u);
}

__global__ void __launch_bounds__(64) dil5x5_kernel(
    const float* __restrict__ x,
    const float* __restrict__ kw,
    float* __restrict__ out)
{
    const int lane   = threadIdx.x & 31;
    const int wlocal = threadIdx.x >> 5;
    const int w      = blockIdx.x * 2 + wlocal;   // warp-task id, 0..8191

    const int img   = w >> 3;          // 0..1023
    const int strip = (w >> 1) & 3;    // 0..3  -> 64-row strip
    const int half  = w & 1;           // 0..1  -> 128-col half

    const int i0 = strip << 6;                    // first output row of strip
    const int j0 = (half << 7) + (lane << 2);     // first of 4 output cols

    float k[25];
#pragma unroll
    for (int t = 0; t < 25; ++t) k[t] = kw[t];

    const float NI = __int_as_float(0xff800000u);

    float acc[5][4];
#pragma unroll
    for (int q = 0; q < 5; ++q)
#pragma unroll
        for (int c = 0; c < 4; ++c) acc[q][c] = NI;

    const float* xim = x   + (size_t)img * (IMG_H * IMG_W);
    float*       oim = out + (size_t)img * (IMG_H * IMG_W);

    // Column-halo validity (loop-invariant). A covers cols j0-4..j0-1 (we
    // use j0-2,j0-1): invalid only when j0==0. C covers j0+4..j0+7 (we use
    // j0+4,j0+5): invalid only when j0==252. B always valid.
    const bool c0ok = (j0 != 0);
    const bool c2ok = (j0 != 252);

    // Row-halo validity: rows i0-2,i0-1 exist unless strip==0; rows
    // i0+64,i0+65 exist unless strip==3.
    const bool topok = (strip != 0);
    const bool botok = (strip != 3);

    const float4 NIV = make_float4(NI, NI, NI, NI);
    float4 Ab[2] = {NIV, NIV}, Bb[2] = {NIV, NIV}, Cb[2] = {NIV, NIV};

    const float* ninf = g_ninf;   // 16 floats of -inf

    // Load a row (base pointer at col j0-4) into buffer DSTP.
#define PREF(DSTP, RP)                                                       \
    {                                                                        \
        const float* _rp = (RP);                                             \
        if (c0ok) Ab[DSTP] = *(const float4*)(_rp);                          \
        Bb[DSTP] = *(const float4*)(_rp + 4);                                \
        if (c2ok) Cb[DSTP] = *(const float4*)(_rp + 8);                      \
    }

    // Apply buffer CUR to the rotating slots selected by compile-time MASK
    // (phase PH); optionally store the completed slot PH (finishes kernel
    // row u=4 this step).
#define MATH(PH, CUR, STOREF, OPTR, MASK)                                    \
    {                                                                        \
        float X[12] = {Ab[CUR].x, Ab[CUR].y, Ab[CUR].z, Ab[CUR].w,           \
                       Bb[CUR].x, Bb[CUR].y, Bb[CUR].z, Bb[CUR].w,           \
                       Cb[CUR].x, Cb[CUR].y, Cb[CUR].z, Cb[CUR].w};          \
        _Pragma("unroll")                                                    \
        for (int q = 0; q < 5; ++q) {                                        \
            if ((((MASK) >> q) & 1) == 0) continue;  /* compile-time */      \
            const int d = (q - (PH) + 5) % 5;   /* compile-time */           \
            const int u = 4 - d;                /* kernel row   */           \
            if (d == 4) {                                                    \
                _Pragma("unroll")                                            \
                for (int c = 0; c < 4; ++c)                                  \
                    acc[q][c] = X[c + 2] + k[u * 5 + 0];                     \
                _Pragma("unroll")                                            \
                for (int v = 1; v < 5; ++v)                                  \
                    _Pragma("unroll")                                        \
                    for (int c = 0; c < 4; ++c)                              \
                        acc[q][c] = fmaxf(acc[q][c], X[c + v + 2] + k[u * 5 + v]); \
            } else {                                                         \
                _Pragma("unroll")                                            \
                for (int v = 0; v < 5; ++v)                                  \
                    _Pragma("unroll")                                        \
                    for (int c = 0; c < 4; ++c)                              \
                        acc[q][c] = fmaxf(acc[q][c], X[c + v + 2] + k[u * 5 + v]); \
            }                                                                \
        }                                                                    \
        if (STOREF)                                                          \
            *(float4*)(OPTR) = make_float4(acc[PH][0], acc[PH][1],           \
                                           acc[PH][2], acc[PH][3]);          \
    }

    // pbase -> row i0-2, col j0-4
    const float* pbase = xim + (ptrdiff_t)(i0 - 2) * IMG_W + (j0 - 4);

    // Prologue: buffer 0 <- row i0-2 (or -inf for the top strip).
    PREF(0, topok ? pbase : ninf)

    // Head, steps s=0..3 (consume rows i0-2..i0+1, no stores). Slot q is
    // initialized at its d==4 step: s0->slot4, s1->slot0, s2->slot1,
    // s3->slot2. Masks include only already-initialized slots.
    PREF(1, topok ? pbase + 1 * IMG_W : ninf)  MATH(0, 0, 0, oim, 0x10)
    PREF(0, pbase + 2 * IMG_W)                 MATH(1, 1, 0, oim, 0x11)
    PREF(1, pbase + 3 * IMG_W)                 MATH(2, 0, 0, oim, 0x13)
    PREF(0, pbase + 4 * IMG_W)                 MATH(3, 1, 0, oim, 0x17)

    // Steady state, steps s=4..63: all slots live, unconditional loads and
    // stores, immediate offsets, pointers bumped once per 10 steps.
    const float* pb = pbase + 5 * IMG_W;             // row i0+3 (first prefetch)
    float*       ob = oim + (size_t)i0 * IMG_W + j0; // row i0 (first store)
    for (int g = 0; g < 6; ++g) {
        PREF(1, pb + 0 * IMG_W)  MATH(4, 0, 1, ob + 0 * IMG_W, 0x1F)
        PREF(0, pb + 1 * IMG_W)  MATH(0, 1, 1, ob + 1 * IMG_W, 0x1F)
        PREF(1, pb + 2 * IMG_W)  MATH(1, 0, 1, ob + 2 * IMG_W, 0x1F)
        PREF(0, pb + 3 * IMG_W)  MATH(2, 1, 1, ob + 3 * IMG_W, 0x1F)
        PREF(1, pb + 4 * IMG_W)  MATH(3, 0, 1, ob + 4 * IMG_W, 0x1F)
        PREF(0, pb + 5 * IMG_W)  MATH(4, 1, 1, ob + 5 * IMG_W, 0x1F)
        PREF(1, pb + 6 * IMG_W)  MATH(0, 0, 1, ob + 6 * IMG_W, 0x1F)
        PREF(0, pb + 7 * IMG_W)  MATH(1, 1, 1, ob + 7 * IMG_W, 0x1F)
        PREF(1, pb + 8 * IMG_W)  MATH(2, 0, 1, ob + 8 * IMG_W, 0x1F)
        PREF(0, pb + 9 * IMG_W)  MATH(3, 1, 1, ob + 9 * IMG_W, 0x1F)
        pb += 10 * IMG_W;
        ob += 10 * IMG_W;
    }
    // After loop: pb -> row i0+63 (next prefetch), ob -> output row i0+60.

    // Tail, steps s=64..67 (phases 4,0,1,2; CUR 0,1,0,1). Emissions:
    // s64->slot4, s65->slot0, s66->slot1, s67->slot2. Slot3 would emit at
    // s68 (doesn't exist) and emitted slots need no further updates, so
    // masks shrink each step. Prefetch rows i0+63 (valid), i0+64, i0+65
    // (valid unless bottom strip), none.
    PREF(1, pb + 0 * IMG_W)                    MATH(4, 0, 1, ob + 0 * IMG_W, 0x17)
    PREF(0, botok ? pb + 1 * IMG_W : ninf)     MATH(0, 1, 1, ob + 1 * IMG_W, 0x07)
    PREF(1, botok ? pb + 2 * IMG_W : ninf)     MATH(1, 0, 1, ob + 2 * IMG_W, 0x06)
    /* no prefetch for the final step */       MATH(2, 1, 1, ob + 3 * IMG_W, 0x04)

#undef PREF
#undef MATH
}

extern "C" void kernel_launch(void* const* d_in, const int* in_sizes, int n_in,
                              void* d_out, int out_size) {
    const float* x  = (const float*)d_in[0];  // (16,64,256,256)
    const float* kw = (const float*)d_in[1];  // (5,5)
    float* out = (float*)d_out;
    fill_ninf_kernel<<<1, 16>>>();
    // 8192 warp-tasks = 1024 images x 4 row-strips x 2 column-halves,
    // 2 warps (one strip: both halves) per 64-thread block.
    dil5x5_kernel<<<4096, 64>>>(x, kw, out);
}

// round 12
// speedup vs baseline: 1.3900x; 1.0043x over previous
#include <cuda_runtime.h>
#include <cstdint>

// SemiConv2d: 5x5 max-plus dilation, 'same' padding with -inf.
// input:  (16, 64, 256, 256) fp32 -> 1024 independent 256x256 images
// kernel: (5, 5) fp32
//
// Row-streaming, 5 rotating accumulator slots, 4 cols/thread (float4 I/O),
// software-prefetched double-buffered loads (R6), boundary peeling (R7),
// masked head/tail + 64-thread blocks (R11).
// R12 change: PACKED f32x2 ADDS along the v (kernel-column) axis.
// acc[c] folds taps in pairs (v0,v1) and (v2,v3) via add.rn.f32x2 with
// 64-bit packed weight pairs (consecutive kernel elements -> natural
// pairs, no weight duplication), plus one scalar tap v4.
// 100 FADD/step -> 40 FADD2 + 20 FADD + ~6 pack MOVs (-16% issue slots).
// f32x2 add is IEEE-identical to scalar FADD.rn; max order unchanged.

#define IMG_H 256
#define IMG_W 256

__device__ __align__(16) float g_ninf[16];

__global__ void fill_ninf_kernel() {
    g_ninf[threadIdx.x] = __int_as_float(0xff800000u);
}

__device__ __forceinline__ unsigned long long pack2(float lo, float hi) {
    unsigned long long r;
    asm("mov.b64 %0, {%1, %2};" : "=l"(r) : "f"(lo), "f"(hi));
    return r;
}
__device__ __forceinline__ unsigned long long addx2(unsigned long long a,
                                                    unsigned long long b) {
    unsigned long long r;
    asm("add.rn.f32x2 %0, %1, %2;" : "=l"(r) : "l"(a), "l"(b));
    return r;
}
__device__ __forceinline__ void unpack2(unsigned long long p,
                                        float& lo, float& hi) {
    asm("mov.b64 {%0, %1}, %2;" : "=f"(lo), "=f"(hi) : "l"(p));
}

__global__ void __launch_bounds__(64) dil5x5_kernel(
    const float* __restrict__ x,
    const float* __restrict__ kw,
    float* __restrict__ out)
{
    const int lane   = threadIdx.x & 31;
    const int wlocal = threadIdx.x >> 5;
    const int w      = blockIdx.x * 2 + wlocal;   // warp-task id, 0..8191

    const int img   = w >> 3;          // 0..1023
    const int strip = (w >> 1) & 3;    // 0..3  -> 64-row strip
    const int half  = w & 1;           // 0..1  -> 128-col half

    const int i0 = strip << 6;                    // first output row of strip
    const int j0 = (half << 7) + (lane << 2);     // first of 4 output cols

    // Weights: per kernel row u, packed pairs (k[u,0],k[u,1]),(k[u,2],k[u,3])
    // and scalar k[u,4]. 10 x 64-bit + 5 scalar = 25 regs, same as scalar k.
    unsigned long long KPa[5], KPb[5];
    float K4[5];
#pragma unroll
    for (int u = 0; u < 5; ++u) {
        const float k0 = kw[u * 5 + 0], k1 = kw[u * 5 + 1];
        const float k2 = kw[u * 5 + 2], k3 = kw[u * 5 + 3];
        KPa[u] = pack2(k0, k1);
        KPb[u] = pack2(k2, k3);
        K4[u]  = kw[u * 5 + 4];
    }

    const float NI = __int_as_float(0xff800000u);

    float acc[5][4];
#pragma unroll
    for (int q = 0; q < 5; ++q)
#pragma unroll
        for (int c = 0; c < 4; ++c) acc[q][c] = NI;

    const float* xim = x   + (size_t)img * (IMG_H * IMG_W);
    float*       oim = out + (size_t)img * (IMG_H * IMG_W);

    // Column-halo validity (loop-invariant). A covers cols j0-4..j0-1 (we
    // use j0-2,j0-1): invalid only when j0==0. C covers j0+4..j0+7 (we use
    // j0+4,j0+5): invalid only when j0==252. B always valid.
    const bool c0ok = (j0 != 0);
    const bool c2ok = (j0 != 252);

    // Row-halo validity: rows i0-2,i0-1 exist unless strip==0; rows
    // i0+64,i0+65 exist unless strip==3.
    const bool topok = (strip != 0);
    const bool botok = (strip != 3);

    const float4 NIV = make_float4(NI, NI, NI, NI);
    float4 Ab[2] = {NIV, NIV}, Bb[2] = {NIV, NIV}, Cb[2] = {NIV, NIV};

    const float* ninf = g_ninf;   // 16 floats of -inf

    // Load a row (base pointer at col j0-4) into buffer DSTP.
#define PREF(DSTP, RP)                                                       \
    {                                                                        \
        const float* _rp = (RP);                                             \
        if (c0ok) Ab[DSTP] = *(const float4*)(_rp);                          \
        Bb[DSTP] = *(const float4*)(_rp + 4);                                \
        if (c2ok) Cb[DSTP] = *(const float4*)(_rp + 8);                      \
    }

    // Apply buffer CUR to the rotating slots selected by compile-time MASK
    // (phase PH); optionally store the completed slot PH.
    // X[m] = col j0-4+m ; acc[c] folds X[c+2..c+6] against kernel row u.
    // Packed: (X[c+2],X[c+3])+KPa[u], (X[c+4],X[c+5])+KPb[u], X[c+6]+K4[u].
#define MATH(PH, CUR, STOREF, OPTR, MASK)                                    \
    {                                                                        \
        float X[10];                                                         \
        X[2] = Ab[CUR].z;  X[3] = Ab[CUR].w;                                 \
        X[4] = Bb[CUR].x;  X[5] = Bb[CUR].y;                                 \
        X[6] = Bb[CUR].z;  X[7] = Bb[CUR].w;                                 \
        X[8] = Cb[CUR].x;  X[9] = Cb[CUR].y;                                 \
        unsigned long long P[8];                                             \
        P[2] = pack2(X[2], X[3]);  P[3] = pack2(X[3], X[4]);                 \
        P[4] = pack2(X[4], X[5]);  P[5] = pack2(X[5], X[6]);                 \
        P[6] = pack2(X[6], X[7]);  P[7] = pack2(X[7], X[8]);                 \
        _Pragma("unroll")                                                    \
        for (int q = 0; q < 5; ++q) {                                        \
            if ((((MASK) >> q) & 1) == 0) continue;  /* compile-time */      \
            const int d = (q - (PH) + 5) % 5;   /* compile-time */           \
            const int u = 4 - d;                /* kernel row   */           \
            _Pragma("unroll")                                                \
            for (int c = 0; c < 4; ++c) {                                    \
                unsigned long long s01 = addx2(P[c + 2], KPa[u]);            \
                unsigned long long s23 = addx2(P[c + 4], KPb[u]);            \
                float a0, a1, a2, a3;                                        \
                unpack2(s01, a0, a1);                                        \
                unpack2(s23, a2, a3);                                        \
                const float a4 = X[c + 6] + K4[u];                           \
                float t = (d == 4) ? a0 : fmaxf(acc[q][c], a0);              \
                t = fmaxf(t, a1);                                            \
                t = fmaxf(t, a2);                                            \
                t = fmaxf(t, a3);                                            \
                acc[q][c] = fmaxf(t, a4);                                    \
            }                                                                \
        }                                                                    \
        if (STOREF)                                                          \
            *(float4*)(OPTR) = make_float4(acc[PH][0], acc[PH][1],           \
                                           acc[PH][2], acc[PH][3]);          \
    }

    // pbase -> row i0-2, col j0-4
    const float* pbase = xim + (ptrdiff_t)(i0 - 2) * IMG_W + (j0 - 4);

    // Prologue: buffer 0 <- row i0-2 (or -inf for the top strip).
    PREF(0, topok ? pbase : ninf)

    // Head, steps s=0..3 (consume rows i0-2..i0+1, no stores). Slot q is
    // initialized at its d==4 step: s0->slot4, s1->slot0, s2->slot1,
    // s3->slot2. Masks include only already-initialized slots.
    PREF(1, topok ? pbase + 1 * IMG_W : ninf)  MATH(0, 0, 0, oim, 0x10)
    PREF(0, pbase + 2 * IMG_W)                 MATH(1, 1, 0, oim, 0x11)
    PREF(1, pbase + 3 * IMG_W)                 MATH(2, 0, 0, oim, 0x13)
    PREF(0, pbase + 4 * IMG_W)                 MATH(3, 1, 0, oim, 0x17)

    // Steady state, steps s=4..63: all slots live, unconditional loads and
    // stores, immediate offsets, pointers bumped once per 10 steps.
    const float* pb = pbase + 5 * IMG_W;             // row i0+3 (first prefetch)
    float*       ob = oim + (size_t)i0 * IMG_W + j0; // row i0 (first store)
    for (int g = 0; g < 6; ++g) {
        PREF(1, pb + 0 * IMG_W)  MATH(4, 0, 1, ob + 0 * IMG_W, 0x1F)
        PREF(0, pb + 1 * IMG_W)  MATH(0, 1, 1, ob + 1 * IMG_W, 0x1F)
        PREF(1, pb + 2 * IMG_W)  MATH(1, 0, 1, ob + 2 * IMG_W, 0x1F)
        PREF(0, pb + 3 * IMG_W)  MATH(2, 1, 1, ob + 3 * IMG_W, 0x1F)
        PREF(1, pb + 4 * IMG_W)  MATH(3, 0, 1, ob + 4 * IMG_W, 0x1F)
        PREF(0, pb + 5 * IMG_W)  MATH(4, 1, 1, ob + 5 * IMG_W, 0x1F)
        PREF(1, pb + 6 * IMG_W)  MATH(0, 0, 1, ob + 6 * IMG_W, 0x1F)
        PREF(0, pb + 7 * IMG_W)  MATH(1, 1, 1, ob + 7 * IMG_W, 0x1F)
        PREF(1, pb + 8 * IMG_W)  MATH(2, 0, 1, ob + 8 * IMG_W, 0x1F)
        PREF(0, pb + 9 * IMG_W)  MATH(3, 1, 1, ob + 9 * IMG_W, 0x1F)
        pb += 10 * IMG_W;
        ob += 10 * IMG_W;
    }
    // After loop: pb -> row i0+63 (next prefetch), ob -> output row i0+60.

    // Tail, steps s=64..67 (phases 4,0,1,2; CUR 0,1,0,1). Emitted slots
    // need no further updates; slot3 never emits. Prefetch rows i0+63
    // (valid), i0+64, i0+65 (valid unless bottom strip), none.
    PREF(1, pb + 0 * IMG_W)                    MATH(4, 0, 1, ob + 0 * IMG_W, 0x17)
    PREF(0, botok ? pb + 1 * IMG_W : ninf)     MATH(0, 1, 1, ob + 1 * IMG_W, 0x07)
    PREF(1, botok ? pb + 2 * IMG_W : ninf)     MATH(1, 0, 1, ob + 2 * IMG_W, 0x06)
    /* no prefetch for the final step */       MATH(2, 1, 1, ob + 3 * IMG_W, 0x04)

#undef PREF
#undef MATH
}

extern "C" void kernel_launch(void* const* d_in, const int* in_sizes, int n_in,
                              void* d_out, int out_size) {
    const float* x  = (const float*)d_in[0];  // (16,64,256,256)
    const float* kw = (const float*)d_in[1];  // (5,5)
    float* out = (float*)d_out;
    fill_ninf_kernel<<<1, 16>>>();
    // 8192 warp-tasks = 1024 images x 4 row-strips x 2 column-halves,
    // 2 warps (one strip: both halves) per 64-thread block.
    dil5x5_kernel<<<4096, 64>>>(x, kw, out);
}